// round 2
// baseline (speedup 1.0000x reference)
#include <cuda_runtime.h>

#define EPSB 1e-5f

// Scratch (device globals — no allocation allowed)
__device__ float g_T[16 * 512 * 64];     // T[b,c,q] = sum_n x*att
__device__ float g_S[16 * 64];           // S[b,q]   = sum_n att
__device__ float g_W2[16 * 64 * 64];     // scale1 * (c1_w @ attention)
__device__ float g_mid[16 * 64 * 4096];  // relu(bn(c1 conv))

// ---------------------------------------------------------------------------
// K0: zero g_T (split-K accumulation target)
// ---------------------------------------------------------------------------
__global__ void k_zeroT() {
    int idx = blockIdx.x * blockDim.x + threadIdx.x;  // 512*256 = 131072 float4
    ((float4*)g_T)[idx] = make_float4(0.f, 0.f, 0.f, 0.f);
}

// ---------------------------------------------------------------------------
// K0b: S[b,q] = sum_n att[b,q,n]
// ---------------------------------------------------------------------------
__global__ void k_sumS(const float* __restrict__ att) {
    int b = blockIdx.x >> 6, q = blockIdx.x & 63, tid = threadIdx.x;
    const float4* p = (const float4*)(att + (size_t)(b * 64 + q) * 4096);
    float s = 0.f;
    for (int i = tid; i < 1024; i += 128) {
        float4 v = p[i];
        s += v.x + v.y + v.z + v.w;
    }
    for (int o = 16; o; o >>= 1) s += __shfl_down_sync(0xffffffffu, s, o);
    __shared__ float ws[4];
    if ((tid & 31) == 0) ws[tid >> 5] = s;
    __syncthreads();
    if (tid == 0) g_S[b * 64 + q] = ws[0] + ws[1] + ws[2] + ws[3];
}

// ---------------------------------------------------------------------------
// K1: T[b,c,q] = sum_n x[b,c,n]*att[b,q,n]   (GEMM, K=4096, split-K=4, atomic)
// grid (8 c-tiles, 4 k-splits, 16 batch), 256 threads, 64x64 tile, 4x4 micro
// ---------------------------------------------------------------------------
__global__ __launch_bounds__(256) void k_T(const float* __restrict__ x,
                                           const float* __restrict__ att) {
    __shared__ float xs[64][68];  // xs[n_local][c]  (transposed)
    __shared__ float as[64][68];  // as[n_local][q]  (transposed)
    const int tid = threadIdx.x;
    const int tx = tid & 15, ty = tid >> 4;
    const int cBase = blockIdx.x * 64;
    const int b = blockIdx.z;
    const int nBase0 = blockIdx.y * 1024;
    const int r0 = tid >> 4, c4 = tid & 15;
    const float* xb = x + (size_t)(b * 512 + cBase) * 4096;
    const float* ab = att + (size_t)(b * 64) * 4096;

    float acc[4][4] = {};

    for (int s = 0; s < 16; s++) {
        int nb = nBase0 + s * 64;
#pragma unroll
        for (int p = 0; p < 4; p++) {
            int r = r0 + p * 16;
            float4 fx = *(const float4*)&xb[(size_t)r * 4096 + nb + c4 * 4];
            xs[c4 * 4 + 0][r] = fx.x; xs[c4 * 4 + 1][r] = fx.y;
            xs[c4 * 4 + 2][r] = fx.z; xs[c4 * 4 + 3][r] = fx.w;
            float4 fa = *(const float4*)&ab[(size_t)r * 4096 + nb + c4 * 4];
            as[c4 * 4 + 0][r] = fa.x; as[c4 * 4 + 1][r] = fa.y;
            as[c4 * 4 + 2][r] = fa.z; as[c4 * 4 + 3][r] = fa.w;
        }
        __syncthreads();
#pragma unroll 16
        for (int kk = 0; kk < 64; kk++) {
            float a[4], bq[4];
            *(float4*)a  = *(const float4*)&xs[kk][ty * 4];
            *(float4*)bq = *(const float4*)&as[kk][tx * 4];
#pragma unroll
            for (int i = 0; i < 4; i++)
#pragma unroll
                for (int j = 0; j < 4; j++) acc[i][j] += a[i] * bq[j];
        }
        __syncthreads();
    }

    float* Tb = g_T + (size_t)(b * 512 + cBase) * 64;
#pragma unroll
    for (int i = 0; i < 4; i++)
#pragma unroll
        for (int j = 0; j < 4; j++)
            atomicAdd(&Tb[(ty * 4 + i) * 64 + tx * 4 + j], acc[i][j]);
}

// ---------------------------------------------------------------------------
// K2: energy = key_w @ T + key_b*S ; softmax(rows over q) ;
//     W2'[o,q] = scale1[o] * sum_k c1_w[o,k]*attn[k,q]
// grid (16 batches), 256 threads
// ---------------------------------------------------------------------------
__global__ __launch_bounds__(256) void k_attn(const float* __restrict__ key_w,
                                              const float* __restrict__ key_b,
                                              const float* __restrict__ c1_w,
                                              const float* __restrict__ c1_gamma,
                                              const float* __restrict__ c1_var) {
    __shared__ float sA[64][68];  // kw chunk transposed [c_local][k]; later energy/attn [k][q]
    __shared__ float sB[64][68];  // T chunk [c_local][q]
    const int tid = threadIdx.x;
    const int tx = tid & 15, ty = tid >> 4;
    const int b = blockIdx.x;
    const int r0 = tid >> 4, c4 = tid & 15;

    float acc[4][4] = {};
    for (int ch = 0; ch < 8; ch++) {
        int cb = ch * 64;
#pragma unroll
        for (int p = 0; p < 4; p++) {
            int r = r0 + p * 16;
            float4 fk = *(const float4*)&key_w[r * 512 + cb + c4 * 4];
            sA[c4 * 4 + 0][r] = fk.x; sA[c4 * 4 + 1][r] = fk.y;
            sA[c4 * 4 + 2][r] = fk.z; sA[c4 * 4 + 3][r] = fk.w;
            float4 ft = *(const float4*)&g_T[(size_t)(b * 512 + cb + r) * 64 + c4 * 4];
            *(float4*)&sB[r][c4 * 4] = ft;
        }
        __syncthreads();
#pragma unroll 16
        for (int cc = 0; cc < 64; cc++) {
            float a[4], bq[4];
            *(float4*)a  = *(const float4*)&sA[cc][ty * 4];
            *(float4*)bq = *(const float4*)&sB[cc][tx * 4];
#pragma unroll
            for (int i = 0; i < 4; i++)
#pragma unroll
                for (int j = 0; j < 4; j++) acc[i][j] += a[i] * bq[j];
        }
        __syncthreads();
    }

    // energy (k = ty*4+i, q = tx*4+j) into sA
#pragma unroll
    for (int i = 0; i < 4; i++)
#pragma unroll
        for (int j = 0; j < 4; j++)
            sA[ty * 4 + i][tx * 4 + j] =
                acc[i][j] + key_b[ty * 4 + i] * g_S[b * 64 + tx * 4 + j];
    __syncthreads();

    // softmax over q, one thread per row
    if (tid < 64) {
        float mx = -1e30f;
        for (int q = 0; q < 64; q++) mx = fmaxf(mx, sA[tid][q]);
        float sum = 0.f;
        for (int q = 0; q < 64; q++) {
            float e = expf(sA[tid][q] - mx);
            sA[tid][q] = e;
            sum += e;
        }
        float inv = 1.f / sum;
        for (int q = 0; q < 64; q++) sA[tid][q] *= inv;
    }
    __syncthreads();

    // W2'[o,q] = scale1[o] * sum_k c1_w[o,k] * attn[k,q]
    for (int t = tid; t < 4096; t += 256) {
        int o = t >> 6, q = t & 63;
        float s = 0.f;
#pragma unroll 16
        for (int k = 0; k < 64; k++) s += c1_w[o * 64 + k] * sA[k][q];
        float sc = c1_gamma[o] * rsqrtf(c1_var[o] + EPSB);
        g_W2[(b * 64 + o) * 64 + q] = sc * s;
    }
}

// ---------------------------------------------------------------------------
// K3: mid[b,o,n] = relu( sum_q W2'[b,o,q]*att[b,q,n] + bias1[o] )
// grid (64 n-tiles, 16 batch), 256 threads, 64x64 tile, 4x4 micro
// ---------------------------------------------------------------------------
__global__ __launch_bounds__(256) void k_mid(const float* __restrict__ att,
                                             const float* __restrict__ c1_b,
                                             const float* __restrict__ c1_gamma,
                                             const float* __restrict__ c1_beta,
                                             const float* __restrict__ c1_mean,
                                             const float* __restrict__ c1_var) {
    __shared__ float w2t[64][68];  // [q][o]
    __shared__ float as[64][68];   // [q][n]
    __shared__ float bi1[64];
    const int tid = threadIdx.x;
    const int tx = tid & 15, ty = tid >> 4;
    const int b = blockIdx.y, nb = blockIdx.x * 64;
    const int r0 = tid >> 4, c4 = tid & 15;

    if (tid < 64) {
        float sc = c1_gamma[tid] * rsqrtf(c1_var[tid] + EPSB);
        bi1[tid] = sc * c1_b[tid] + c1_beta[tid] - c1_mean[tid] * sc;
    }
#pragma unroll
    for (int p = 0; p < 4; p++) {
        int r = r0 + p * 16;
        float4 fw = *(const float4*)&g_W2[(size_t)(b * 64 + r) * 64 + c4 * 4];
        w2t[c4 * 4 + 0][r] = fw.x; w2t[c4 * 4 + 1][r] = fw.y;
        w2t[c4 * 4 + 2][r] = fw.z; w2t[c4 * 4 + 3][r] = fw.w;
        float4 fa = *(const float4*)&att[(size_t)(b * 64 + r) * 4096 + nb + c4 * 4];
        *(float4*)&as[r][c4 * 4] = fa;
    }
    __syncthreads();

    float acc[4][4] = {};
#pragma unroll 16
    for (int q = 0; q < 64; q++) {
        float a[4], bq[4];
        *(float4*)a  = *(const float4*)&w2t[q][ty * 4];
        *(float4*)bq = *(const float4*)&as[q][tx * 4];
#pragma unroll
        for (int i = 0; i < 4; i++)
#pragma unroll
            for (int j = 0; j < 4; j++) acc[i][j] += a[i] * bq[j];
    }

    float* mb = g_mid + (size_t)(b * 64) * 4096 + nb;
#pragma unroll
    for (int i = 0; i < 4; i++) {
        int o = ty * 4 + i;
        float bi = bi1[o];
        float4 v;
        v.x = fmaxf(acc[i][0] + bi, 0.f);
        v.y = fmaxf(acc[i][1] + bi, 0.f);
        v.z = fmaxf(acc[i][2] + bi, 0.f);
        v.w = fmaxf(acc[i][3] + bi, 0.f);
        *(float4*)&mb[(size_t)o * 4096 + tx * 4] = v;
    }
}

// ---------------------------------------------------------------------------
// K4: out[b,o,n] = relu( scale2[o]*(c2_w[o,:] . [mid;x][:,n] + c2_b[o]) + shift2[o] )
// grid (32 n-tiles, 4 m-tiles, 16 batch), 256 threads,
// 128x128 tile, K-tile 16, 8x8 micro, register-staged global prefetch
// ---------------------------------------------------------------------------
__global__ __launch_bounds__(256, 2) void k_out(const float* __restrict__ x,
                                                const float* __restrict__ c2_w,
                                                const float* __restrict__ c2_b,
                                                const float* __restrict__ c2_gamma,
                                                const float* __restrict__ c2_beta,
                                                const float* __restrict__ c2_mean,
                                                const float* __restrict__ c2_var,
                                                float* __restrict__ out) {
    __shared__ float As[16][132];  // [k][m] transposed
    __shared__ float Bs[16][128];  // [k][n]
    __shared__ float sc2[128], bi2[128];

    const int tid = threadIdx.x;
    const int tx = tid & 15, ty = tid >> 4;
    const int nBase = blockIdx.x * 128, mBase = blockIdx.y * 128;
    const int b = blockIdx.z;

    if (tid < 128) {
        int m = mBase + tid;
        float sc = c2_gamma[m] * rsqrtf(c2_var[m] + EPSB);
        sc2[tid] = sc;
        bi2[tid] = sc * c2_b[m] + c2_beta[m] - c2_mean[m] * sc;
    }

    const int am = tid >> 1;          // A row (m) 0..127
    const int ac0 = (tid & 1) * 2;    // A float4 col pair {0,1} or {2,3}
    const int bk = tid >> 5;          // B rows bk, bk+8
    const int bc = tid & 31;          // B float4 col

    float acc[8][8] = {};
    float4 ra0, ra1, rb0, rb1;

    // prologue load (kBase = 0 -> B comes from g_mid)
    {
        const float* aw = &c2_w[(size_t)(mBase + am) * 576];
        ra0 = *(const float4*)&aw[ac0 * 4];
        ra1 = *(const float4*)&aw[(ac0 + 1) * 4];
        const float* base = g_mid + (size_t)(b * 64) * 4096;
        rb0 = *(const float4*)&base[(size_t)bk * 4096 + nBase + bc * 4];
        rb1 = *(const float4*)&base[(size_t)(bk + 8) * 4096 + nBase + bc * 4];
    }

    for (int s = 0; s < 36; s++) {
        // commit staged regs to smem
        As[ac0 * 4 + 0][am] = ra0.x; As[ac0 * 4 + 1][am] = ra0.y;
        As[ac0 * 4 + 2][am] = ra0.z; As[ac0 * 4 + 3][am] = ra0.w;
        As[ac0 * 4 + 4][am] = ra1.x; As[ac0 * 4 + 5][am] = ra1.y;
        As[ac0 * 4 + 6][am] = ra1.z; As[ac0 * 4 + 7][am] = ra1.w;
        *(float4*)&Bs[bk][bc * 4]     = rb0;
        *(float4*)&Bs[bk + 8][bc * 4] = rb1;
        __syncthreads();

        if (s < 35) {
            int kB = (s + 1) * 16;
            const float* aw = &c2_w[(size_t)(mBase + am) * 576 + kB];
            ra0 = *(const float4*)&aw[ac0 * 4];
            ra1 = *(const float4*)&aw[(ac0 + 1) * 4];
            const float* base = (kB < 64)
                                    ? (g_mid + (size_t)(b * 64 + kB) * 4096)
                                    : (x + (size_t)(b * 512 + kB - 64) * 4096);
            rb0 = *(const float4*)&base[(size_t)bk * 4096 + nBase + bc * 4];
            rb1 = *(const float4*)&base[(size_t)(bk + 8) * 4096 + nBase + bc * 4];
        }

#pragma unroll
        for (int kk = 0; kk < 16; kk++) {
            float a[8], bb[8];
            *(float4*)&a[0]  = *(const float4*)&As[kk][ty * 8];
            *(float4*)&a[4]  = *(const float4*)&As[kk][ty * 8 + 4];
            *(float4*)&bb[0] = *(const float4*)&Bs[kk][tx * 8];
            *(float4*)&bb[4] = *(const float4*)&Bs[kk][tx * 8 + 4];
#pragma unroll
            for (int i = 0; i < 8; i++)
#pragma unroll
                for (int j = 0; j < 8; j++) acc[i][j] += a[i] * bb[j];
        }
        __syncthreads();
    }

    float* ob = out + (size_t)(b * 512 + mBase) * 4096 + nBase;
#pragma unroll
    for (int i = 0; i < 8; i++) {
        int m = ty * 8 + i;
        float sc = sc2[m], bi = bi2[m];
        float4 v0, v1;
        v0.x = fmaxf(acc[i][0] * sc + bi, 0.f);
        v0.y = fmaxf(acc[i][1] * sc + bi, 0.f);
        v0.z = fmaxf(acc[i][2] * sc + bi, 0.f);
        v0.w = fmaxf(acc[i][3] * sc + bi, 0.f);
        v1.x = fmaxf(acc[i][4] * sc + bi, 0.f);
        v1.y = fmaxf(acc[i][5] * sc + bi, 0.f);
        v1.z = fmaxf(acc[i][6] * sc + bi, 0.f);
        v1.w = fmaxf(acc[i][7] * sc + bi, 0.f);
        *(float4*)&ob[(size_t)m * 4096 + tx * 8]     = v0;
        *(float4*)&ob[(size_t)m * 4096 + tx * 8 + 4] = v1;
    }
}

// ---------------------------------------------------------------------------
extern "C" void kernel_launch(void* const* d_in, const int* in_sizes, int n_in,
                              void* d_out, int out_size) {
    const float* x        = (const float*)d_in[0];
    const float* att      = (const float*)d_in[1];
    const float* key_w    = (const float*)d_in[2];
    const float* key_b    = (const float*)d_in[3];
    const float* c1_w     = (const float*)d_in[4];
    const float* c1_b     = (const float*)d_in[5];
    const float* c1_gamma = (const float*)d_in[6];
    const float* c1_beta  = (const float*)d_in[7];
    const float* c1_mean  = (const float*)d_in[8];
    const float* c1_var   = (const float*)d_in[9];
    const float* c2_w     = (const float*)d_in[10];
    const float* c2_b     = (const float*)d_in[11];
    const float* c2_gamma = (const float*)d_in[12];
    const float* c2_beta  = (const float*)d_in[13];
    const float* c2_mean  = (const float*)d_in[14];
    const float* c2_var   = (const float*)d_in[15];
    float* out = (float*)d_out;

    k_zeroT<<<512, 256>>>();
    k_sumS<<<1024, 128>>>(att);
    k_T<<<dim3(8, 4, 16), 256>>>(x, att);
    k_attn<<<16, 256>>>(key_w, key_b, c1_w, c1_gamma, c1_var);
    k_mid<<<dim3(64, 16), 256>>>(att, c1_b, c1_gamma, c1_beta, c1_mean, c1_var);
    k_out<<<dim3(32, 4, 16), 256>>>(x, c2_w, c2_b, c2_gamma, c2_beta, c2_mean,
                                    c2_var, out);
}

// round 4
// speedup vs baseline: 1.6162x; 1.6162x over previous
#include <cuda_runtime.h>
#include <cstdint>

#define EPSB 1e-5f

// Scratch (device globals — no allocation allowed)
__device__ float g_T[16 * 512 * 64];     // T[b,c,q] = sum_n x*att
__device__ float g_S[16 * 64];           // S[b,q]   = sum_n att
__device__ float g_W2[16 * 64 * 64];     // scale1 * (c1_w @ attention)
__device__ float g_mid[16 * 64 * 4096];  // relu(bn(c1 conv))

__device__ __forceinline__ uint32_t f2tf32(float f) {
    uint32_t u;
    asm("cvt.rna.tf32.f32 %0, %1;" : "=r"(u) : "f"(f));
    return u;
}
__device__ __forceinline__ void mma_tf32(float* c, uint32_t a0, uint32_t a1,
                                         uint32_t a2, uint32_t a3, uint32_t b0,
                                         uint32_t b1) {
    asm volatile(
        "mma.sync.aligned.m16n8k8.row.col.f32.tf32.tf32.f32 "
        "{%0,%1,%2,%3}, {%4,%5,%6,%7}, {%8,%9}, {%0,%1,%2,%3};"
        : "+f"(c[0]), "+f"(c[1]), "+f"(c[2]), "+f"(c[3])
        : "r"(a0), "r"(a1), "r"(a2), "r"(a3), "r"(b0), "r"(b1));
}

// ---------------------------------------------------------------------------
// K0: zero g_T
// ---------------------------------------------------------------------------
__global__ void k_zeroT() {
    int idx = blockIdx.x * blockDim.x + threadIdx.x;
    ((float4*)g_T)[idx] = make_float4(0.f, 0.f, 0.f, 0.f);
}

// ---------------------------------------------------------------------------
// K0b: S[b,q] = sum_n att[b,q,n]
// ---------------------------------------------------------------------------
__global__ void k_sumS(const float* __restrict__ att) {
    int b = blockIdx.x >> 6, q = blockIdx.x & 63, tid = threadIdx.x;
    const float4* p = (const float4*)(att + (size_t)(b * 64 + q) * 4096);
    float s = 0.f;
    for (int i = tid; i < 1024; i += 128) {
        float4 v = p[i];
        s += v.x + v.y + v.z + v.w;
    }
    for (int o = 16; o; o >>= 1) s += __shfl_down_sync(0xffffffffu, s, o);
    __shared__ float ws[4];
    if ((tid & 31) == 0) ws[tid >> 5] = s;
    __syncthreads();
    if (tid == 0) g_S[b * 64 + q] = ws[0] + ws[1] + ws[2] + ws[3];
}

// ---------------------------------------------------------------------------
// K1: T[b,c,q] = sum_n x[b,c,n]*att[b,q,n]   (fp32, split-K=4, atomic)
// ---------------------------------------------------------------------------
__global__ __launch_bounds__(256) void k_T(const float* __restrict__ x,
                                           const float* __restrict__ att) {
    __shared__ float xs[64][68];
    __shared__ float as[64][68];
    const int tid = threadIdx.x;
    const int tx = tid & 15, ty = tid >> 4;
    const int cBase = blockIdx.x * 64;
    const int b = blockIdx.z;
    const int nBase0 = blockIdx.y * 1024;
    const int r0 = tid >> 4, c4 = tid & 15;
    const float* xb = x + (size_t)(b * 512 + cBase) * 4096;
    const float* ab = att + (size_t)(b * 64) * 4096;

    float acc[4][4] = {};

    for (int s = 0; s < 16; s++) {
        int nb = nBase0 + s * 64;
#pragma unroll
        for (int p = 0; p < 4; p++) {
            int r = r0 + p * 16;
            float4 fx = *(const float4*)&xb[(size_t)r * 4096 + nb + c4 * 4];
            xs[c4 * 4 + 0][r] = fx.x; xs[c4 * 4 + 1][r] = fx.y;
            xs[c4 * 4 + 2][r] = fx.z; xs[c4 * 4 + 3][r] = fx.w;
            float4 fa = *(const float4*)&ab[(size_t)r * 4096 + nb + c4 * 4];
            as[c4 * 4 + 0][r] = fa.x; as[c4 * 4 + 1][r] = fa.y;
            as[c4 * 4 + 2][r] = fa.z; as[c4 * 4 + 3][r] = fa.w;
        }
        __syncthreads();
#pragma unroll 16
        for (int kk = 0; kk < 64; kk++) {
            float a[4], bq[4];
            *(float4*)a = *(const float4*)&xs[kk][ty * 4];
            *(float4*)bq = *(const float4*)&as[kk][tx * 4];
#pragma unroll
            for (int i = 0; i < 4; i++)
#pragma unroll
                for (int j = 0; j < 4; j++) acc[i][j] += a[i] * bq[j];
        }
        __syncthreads();
    }

    float* Tb = g_T + (size_t)(b * 512 + cBase) * 64;
#pragma unroll
    for (int i = 0; i < 4; i++)
#pragma unroll
        for (int j = 0; j < 4; j++)
            atomicAdd(&Tb[(ty * 4 + i) * 64 + tx * 4 + j], acc[i][j]);
}

// ---------------------------------------------------------------------------
// K2: energy = key_w @ T + key_b*S ; softmax ; W2' = scale1*(c1_w @ attn)
// ---------------------------------------------------------------------------
__global__ __launch_bounds__(256) void k_attn(const float* __restrict__ key_w,
                                              const float* __restrict__ key_b,
                                              const float* __restrict__ c1_w,
                                              const float* __restrict__ c1_gamma,
                                              const float* __restrict__ c1_var) {
    __shared__ float sA[64][68];
    __shared__ float sB[64][68];
    const int tid = threadIdx.x;
    const int tx = tid & 15, ty = tid >> 4;
    const int b = blockIdx.x;
    const int r0 = tid >> 4, c4 = tid & 15;

    float acc[4][4] = {};
    for (int ch = 0; ch < 8; ch++) {
        int cb = ch * 64;
#pragma unroll
        for (int p = 0; p < 4; p++) {
            int r = r0 + p * 16;
            float4 fk = *(const float4*)&key_w[r * 512 + cb + c4 * 4];
            sA[c4 * 4 + 0][r] = fk.x; sA[c4 * 4 + 1][r] = fk.y;
            sA[c4 * 4 + 2][r] = fk.z; sA[c4 * 4 + 3][r] = fk.w;
            float4 ft =
                *(const float4*)&g_T[(size_t)(b * 512 + cb + r) * 64 + c4 * 4];
            *(float4*)&sB[r][c4 * 4] = ft;
        }
        __syncthreads();
#pragma unroll 16
        for (int cc = 0; cc < 64; cc++) {
            float a[4], bq[4];
            *(float4*)a = *(const float4*)&sA[cc][ty * 4];
            *(float4*)bq = *(const float4*)&sB[cc][tx * 4];
#pragma unroll
            for (int i = 0; i < 4; i++)
#pragma unroll
                for (int j = 0; j < 4; j++) acc[i][j] += a[i] * bq[j];
        }
        __syncthreads();
    }

#pragma unroll
    for (int i = 0; i < 4; i++)
#pragma unroll
        for (int j = 0; j < 4; j++)
            sA[ty * 4 + i][tx * 4 + j] =
                acc[i][j] + key_b[ty * 4 + i] * g_S[b * 64 + tx * 4 + j];
    __syncthreads();

    if (tid < 64) {
        float mx = -1e30f;
        for (int q = 0; q < 64; q++) mx = fmaxf(mx, sA[tid][q]);
        float sum = 0.f;
        for (int q = 0; q < 64; q++) {
            float e = expf(sA[tid][q] - mx);
            sA[tid][q] = e;
            sum += e;
        }
        float inv = 1.f / sum;
        for (int q = 0; q < 64; q++) sA[tid][q] *= inv;
    }
    __syncthreads();

    for (int t = tid; t < 4096; t += 256) {
        int o = t >> 6, q = t & 63;
        float s = 0.f;
#pragma unroll 16
        for (int k = 0; k < 64; k++) s += c1_w[o * 64 + k] * sA[k][q];
        float sc = c1_gamma[o] * rsqrtf(c1_var[o] + EPSB);
        g_W2[(b * 64 + o) * 64 + q] = sc * s;
    }
}

// ---------------------------------------------------------------------------
// K3: mid[b,o,n] = relu( sum_q W2'[b,o,q]*att[b,q,n] + bias1[o] )
// ---------------------------------------------------------------------------
__global__ __launch_bounds__(256) void k_mid(const float* __restrict__ att,
                                             const float* __restrict__ c1_b,
                                             const float* __restrict__ c1_gamma,
                                             const float* __restrict__ c1_beta,
                                             const float* __restrict__ c1_mean,
                                             const float* __restrict__ c1_var) {
    __shared__ float w2t[64][68];
    __shared__ float as[64][68];
    __shared__ float bi1[64];
    const int tid = threadIdx.x;
    const int tx = tid & 15, ty = tid >> 4;
    const int b = blockIdx.y, nb = blockIdx.x * 64;
    const int r0 = tid >> 4, c4 = tid & 15;

    if (tid < 64) {
        float sc = c1_gamma[tid] * rsqrtf(c1_var[tid] + EPSB);
        bi1[tid] = sc * c1_b[tid] + c1_beta[tid] - c1_mean[tid] * sc;
    }
#pragma unroll
    for (int p = 0; p < 4; p++) {
        int r = r0 + p * 16;
        float4 fw = *(const float4*)&g_W2[(size_t)(b * 64 + r) * 64 + c4 * 4];
        w2t[c4 * 4 + 0][r] = fw.x; w2t[c4 * 4 + 1][r] = fw.y;
        w2t[c4 * 4 + 2][r] = fw.z; w2t[c4 * 4 + 3][r] = fw.w;
        float4 fa = *(const float4*)&att[(size_t)(b * 64 + r) * 4096 + nb + c4 * 4];
        *(float4*)&as[r][c4 * 4] = fa;
    }
    __syncthreads();

    float acc[4][4] = {};
#pragma unroll 16
    for (int q = 0; q < 64; q++) {
        float a[4], bq[4];
        *(float4*)a = *(const float4*)&w2t[q][ty * 4];
        *(float4*)bq = *(const float4*)&as[q][tx * 4];
#pragma unroll
        for (int i = 0; i < 4; i++)
#pragma unroll
            for (int j = 0; j < 4; j++) acc[i][j] += a[i] * bq[j];
    }

    float* mb = g_mid + (size_t)(b * 64) * 4096 + nb;
#pragma unroll
    for (int i = 0; i < 4; i++) {
        int o = ty * 4 + i;
        float bi = bi1[o];
        float4 v;
        v.x = fmaxf(acc[i][0] + bi, 0.f);
        v.y = fmaxf(acc[i][1] + bi, 0.f);
        v.z = fmaxf(acc[i][2] + bi, 0.f);
        v.w = fmaxf(acc[i][3] + bi, 0.f);
        *(float4*)&mb[(size_t)o * 4096 + tx * 4] = v;
    }
}

// ---------------------------------------------------------------------------
// K4 (mma.sync tf32): out = relu(scale2*(c2_w @ [mid;x]) + bias2')
// 128x128 block tile, 8 warps (2m x 4n), warp tile 64x32 via m16n8k8,
// K=576 in 36 chunks of 16, double-buffered smem (136-float pitch).
// grid (32 n, 4 m, 16 b), 256 threads.
// ---------------------------------------------------------------------------
__global__ __launch_bounds__(256, 2) void k_out_mma(
    const float* __restrict__ x, const float* __restrict__ c2_w,
    const float* __restrict__ c2_b, const float* __restrict__ c2_gamma,
    const float* __restrict__ c2_beta, const float* __restrict__ c2_mean,
    const float* __restrict__ c2_var, float* __restrict__ out) {
    __shared__ float sA[2][16][136];  // [k][m]
    __shared__ float sB[2][16][136];  // [k][n]
    __shared__ float sc2s[128], bi2s[128];

    const int tid = threadIdx.x;
    const int wid = tid >> 5, lane = tid & 31;
    const int gid = lane >> 2, tig = lane & 3;
    const int wm = (wid >> 2) * 64, wn = (wid & 3) * 32;
    const int nBase = blockIdx.x * 128, mBase = blockIdx.y * 128;
    const int b = blockIdx.z;
    const float* xb = x + (size_t)b * 512 * 4096;
    const float* midb = g_mid + (size_t)b * 64 * 4096;

    if (tid < 128) {
        int m = mBase + tid;
        float sc = c2_gamma[m] * rsqrtf(c2_var[m] + EPSB);
        sc2s[tid] = sc;
        bi2s[tid] = sc * c2_b[m] + c2_beta[m] - c2_mean[m] * sc;
    }

    // producer thread mapping
    const int rowA = tid & 127, kqA = tid >> 7;  // A: rows, k-quarter pair
    const int kB = tid >> 4;                     // B: k row 0..15
    const int cB0 = (tid & 15) * 4;              // B: col (x4), second at +64

    float4 pa[2], pb[2];

    // prefetch chunk kc0 into registers
#define PREFETCH(kc0)                                                         \
    {                                                                         \
        const float* aw = &c2_w[(size_t)(mBase + rowA) * 576 + (kc0)];        \
        pa[0] = *(const float4*)&aw[(kqA * 2 + 0) * 4];                       \
        pa[1] = *(const float4*)&aw[(kqA * 2 + 1) * 4];                       \
        int kg = (kc0) + kB;                                                  \
        const float* src = (kg < 64) ? (midb + (size_t)kg * 4096)             \
                                     : (xb + (size_t)(kg - 64) * 4096);      \
        pb[0] = *(const float4*)&src[nBase + cB0];                            \
        pb[1] = *(const float4*)&src[nBase + cB0 + 64];                       \
    }

    // store staged registers into smem stage st (with tf32 rounding)
#define STORE_STAGE(st)                                                       \
    {                                                                         \
        _Pragma("unroll") for (int r = 0; r < 2; r++) {                       \
            int kq = kqA * 2 + r;                                             \
            float* col = &sA[st][kq * 4][rowA];                               \
            const float* pv = (const float*)&pa[r];                           \
            _Pragma("unroll") for (int i = 0; i < 4; i++)                     \
                col[i * 136] = __uint_as_float(f2tf32(pv[i]));                \
            const float* qv = (const float*)&pb[r];                           \
            float* brow = &sB[st][kB][cB0 + r * 64];                          \
            _Pragma("unroll") for (int i = 0; i < 4; i++)                     \
                brow[i] = __uint_as_float(f2tf32(qv[i]));                     \
        }                                                                     \
    }

    float acc[4][4][4] = {};

    PREFETCH(0);
    STORE_STAGE(0);
    __syncthreads();

#pragma unroll 1
    for (int c = 0; c < 36; c++) {
        const int s = c & 1;
        if (c < 35) PREFETCH((c + 1) * 16);

#pragma unroll
        for (int h = 0; h < 2; h++) {
            const int ks = h * 8;
            uint32_t b0[4], b1[4];
#pragma unroll
            for (int fn = 0; fn < 4; fn++) {
                b0[fn] = __float_as_uint(sB[s][ks + tig][wn + fn * 8 + gid]);
                b1[fn] =
                    __float_as_uint(sB[s][ks + tig + 4][wn + fn * 8 + gid]);
            }
#pragma unroll
            for (int fm = 0; fm < 4; fm++) {
                const int m0 = wm + fm * 16 + gid;
                uint32_t a0 = __float_as_uint(sA[s][ks + tig][m0]);
                uint32_t a1 = __float_as_uint(sA[s][ks + tig][m0 + 8]);
                uint32_t a2 = __float_as_uint(sA[s][ks + tig + 4][m0]);
                uint32_t a3 = __float_as_uint(sA[s][ks + tig + 4][m0 + 8]);
#pragma unroll
                for (int fn = 0; fn < 4; fn++)
                    mma_tf32(acc[fm][fn], a0, a1, a2, a3, b0[fn], b1[fn]);
            }
        }

        if (c < 35) STORE_STAGE((c + 1) & 1);
        __syncthreads();
    }

    // epilogue: BN scale/bias + relu from C fragments
    float* outb = out + (size_t)b * 512 * 4096;
#pragma unroll
    for (int fm = 0; fm < 4; fm++) {
        const int ml0 = wm + fm * 16 + gid;
        const float s0 = sc2s[ml0], v0 = bi2s[ml0];
        const float s1 = sc2s[ml0 + 8], v1 = bi2s[ml0 + 8];
        float* r0 = outb + (size_t)(mBase + ml0) * 4096 + nBase + wn;
        float* r1 = r0 + (size_t)8 * 4096;
#pragma unroll
        for (int fn = 0; fn < 4; fn++) {
            const int nc = fn * 8 + 2 * tig;
            float2 w0, w1;
            w0.x = fmaxf(acc[fm][fn][0] * s0 + v0, 0.f);
            w0.y = fmaxf(acc[fm][fn][1] * s0 + v0, 0.f);
            w1.x = fmaxf(acc[fm][fn][2] * s1 + v1, 0.f);
            w1.y = fmaxf(acc[fm][fn][3] * s1 + v1, 0.f);
            *(float2*)&r0[nc] = w0;
            *(float2*)&r1[nc] = w1;
        }
    }
}

// ---------------------------------------------------------------------------
extern "C" void kernel_launch(void* const* d_in, const int* in_sizes, int n_in,
                              void* d_out, int out_size) {
    const float* x        = (const float*)d_in[0];
    const float* att      = (const float*)d_in[1];
    const float* key_w    = (const float*)d_in[2];
    const float* key_b    = (const float*)d_in[3];
    const float* c1_w     = (const float*)d_in[4];
    const float* c1_b     = (const float*)d_in[5];
    const float* c1_gamma = (const float*)d_in[6];
    const float* c1_beta  = (const float*)d_in[7];
    const float* c1_mean  = (const float*)d_in[8];
    const float* c1_var   = (const float*)d_in[9];
    const float* c2_w     = (const float*)d_in[10];
    const float* c2_b     = (const float*)d_in[11];
    const float* c2_gamma = (const float*)d_in[12];
    const float* c2_beta  = (const float*)d_in[13];
    const float* c2_mean  = (const float*)d_in[14];
    const float* c2_var   = (const float*)d_in[15];
    float* out = (float*)d_out;

    k_zeroT<<<512, 256>>>();
    k_sumS<<<1024, 128>>>(att);
    k_T<<<dim3(8, 4, 16), 256>>>(x, att);
    k_attn<<<16, 256>>>(key_w, key_b, c1_w, c1_gamma, c1_var);
    k_mid<<<dim3(64, 16), 256>>>(att, c1_b, c1_gamma, c1_beta, c1_mean, c1_var);
    k_out_mma<<<dim3(32, 4, 16), 256>>>(x, c2_w, c2_b, c2_gamma, c2_beta,
                                        c2_mean, c2_var, out);
}

// round 5
// speedup vs baseline: 2.3366x; 1.4457x over previous
#include <cuda_runtime.h>
#include <cstdint>

#define EPSB 1e-5f

// Scratch (device globals — no allocation allowed)
__device__ float g_x32[16 * 512 * 4096];   // tf32-rounded x  (128MB)
__device__ float g_att32[16 * 64 * 4096];  // tf32-rounded att (16MB)
__device__ float g_w2c[512 * 576];         // tf32-rounded c2_w
__device__ float g_T[16 * 512 * 64];       // T[b,c,q] = sum_n x*att
__device__ float g_E[16 * 64 * 64];        // energy (pre-bias)
__device__ float g_S[16 * 64];             // S[b,q] = sum_n att
__device__ float g_W2[16 * 64 * 64];       // scale1 * (c1_w @ attention)
__device__ float g_mid[16 * 64 * 4096];    // relu(bn(c1 conv)), tf32-rounded

// ===========================================================================
// helpers
// ===========================================================================
__device__ __forceinline__ uint32_t f2tf32(float f) {
    uint32_t u;
    asm("cvt.rna.tf32.f32 %0, %1;" : "=r"(u) : "f"(f));
    return u;
}
__device__ __forceinline__ float4 cvt4(float4 v) {
    v.x = __uint_as_float(f2tf32(v.x));
    v.y = __uint_as_float(f2tf32(v.y));
    v.z = __uint_as_float(f2tf32(v.z));
    v.w = __uint_as_float(f2tf32(v.w));
    return v;
}
__device__ __forceinline__ void mma_tf32(float* c, uint32_t a0, uint32_t a1,
                                         uint32_t a2, uint32_t a3, uint32_t b0,
                                         uint32_t b1) {
    asm volatile(
        "mma.sync.aligned.m16n8k8.row.col.f32.tf32.tf32.f32 "
        "{%0,%1,%2,%3}, {%4,%5,%6,%7}, {%8,%9}, {%0,%1,%2,%3};"
        : "+f"(c[0]), "+f"(c[1]), "+f"(c[2]), "+f"(c[3])
        : "r"(a0), "r"(a1), "r"(a2), "r"(a3), "r"(b0), "r"(b1));
}
__device__ __forceinline__ uint32_t smem_u32(const void* p) {
    uint32_t a;
    asm("{ .reg .u64 t; cvta.to.shared.u64 t, %1; cvt.u32.u64 %0, t; }"
        : "=r"(a) : "l"(p));
    return a;
}
__device__ __forceinline__ void cp16(uint32_t dst, const void* src) {
    asm volatile("cp.async.cg.shared.global [%0], [%1], 16;" ::"r"(dst),
                 "l"(src));
}
#define CP_COMMIT() asm volatile("cp.async.commit_group;" ::: "memory")
#define CP_WAIT(n) asm volatile("cp.async.wait_group %0;" ::"n"(n) : "memory")
#define FRAG_U(p) __float_as_uint(p)

// ---------------------------------------------------------------------------
// K_prep: tf32-round x/att/c2_w into globals; zero g_T and g_E
// ---------------------------------------------------------------------------
__global__ void k_prep(const float* __restrict__ x,
                       const float* __restrict__ att,
                       const float* __restrict__ c2w) {
    const size_t NX = 8388608, NA = 1048576, NW = 73728, NT = 131072,
                 NE = 16384;
    const size_t TOT = NX + NA + NW + NT + NE;
    size_t i = (size_t)blockIdx.x * blockDim.x + threadIdx.x;
    size_t stride = (size_t)gridDim.x * blockDim.x;
    const float4 z = make_float4(0.f, 0.f, 0.f, 0.f);
    for (size_t t = i; t < TOT; t += stride) {
        if (t < NX) {
            ((float4*)g_x32)[t] = cvt4(((const float4*)x)[t]);
        } else if (t < NX + NA) {
            size_t u = t - NX;
            ((float4*)g_att32)[u] = cvt4(((const float4*)att)[u]);
        } else if (t < NX + NA + NW) {
            size_t u = t - NX - NA;
            ((float4*)g_w2c)[u] = cvt4(((const float4*)c2w)[u]);
        } else if (t < NX + NA + NW + NT) {
            ((float4*)g_T)[t - NX - NA - NW] = z;
        } else {
            ((float4*)g_E)[t - NX - NA - NW - NT] = z;
        }
    }
}

// ---------------------------------------------------------------------------
// K_sumS: S[b,q] = sum_n att[b,q,n]
// ---------------------------------------------------------------------------
__global__ void k_sumS(const float* __restrict__ att) {
    int b = blockIdx.x >> 6, q = blockIdx.x & 63, tid = threadIdx.x;
    const float4* p = (const float4*)(att + (size_t)(b * 64 + q) * 4096);
    float s = 0.f;
    for (int i = tid; i < 1024; i += 128) {
        float4 v = p[i];
        s += v.x + v.y + v.z + v.w;
    }
    for (int o = 16; o; o >>= 1) s += __shfl_down_sync(0xffffffffu, s, o);
    __shared__ float ws[4];
    if ((tid & 31) == 0) ws[tid >> 5] = s;
    __syncthreads();
    if (tid == 0) g_S[b * 64 + q] = ws[0] + ws[1] + ws[2] + ws[3];
}

// ---------------------------------------------------------------------------
// K_T (mma tf32 + cp.async): T[b,c,q] = sum_n x*att, split-K=4 atomic
// Block 128m(c) x 64n(q), K-chunk 16, 64 chunks, 4 stages.
// 8 warps: 4m x 2n, warp tile 32x32. grid (4 ksplit, 4 msplit, 16 b).
// A smem [m128][k16 pitch20]; B smem [n64][k16 pitch20].
// ---------------------------------------------------------------------------
__global__ __launch_bounds__(256, 2) void k_T_mma() {
    extern __shared__ float dsm[];
    float* sA = dsm;           // 4 stages x 2560 floats
    float* sB = dsm + 10240;   // 4 stages x 1280 floats
    const uint32_t sAu = smem_u32(sA), sBu = smem_u32(sB);

    const int tid = threadIdx.x;
    const int wid = tid >> 5, lane = tid & 31;
    const int gid = lane >> 2, tig = lane & 3;
    const int wm = (wid >> 1) * 32, wn = (wid & 1) * 32;
    const int kBase = blockIdx.x * 1024;
    const int mBase = blockIdx.y * 128;
    const int b = blockIdx.z;

    const float* Ag = g_x32 + ((size_t)(b * 512 + mBase)) * 4096 + kBase;
    const float* Bg = g_att32 + ((size_t)(b * 64)) * 4096 + kBase;

    // producer: A 512 chunks (2/thread), B 256 chunks (1/thread)
#define KT_LOAD(st, c)                                                        \
    {                                                                         \
        _Pragma("unroll") for (int j = 0; j < 2; j++) {                       \
            int idx = tid * 2 + j;                                            \
            int row = idx >> 2, ch = idx & 3;                                 \
            cp16(sAu + (st)*10240 + row * 80 + ch * 16,                       \
                 Ag + (size_t)row * 4096 + (c)*16 + ch * 4);                  \
        }                                                                     \
        {                                                                     \
            int row = tid >> 2, ch = tid & 3;                                 \
            cp16(sBu + (st)*5120 + row * 80 + ch * 16,                        \
                 Bg + (size_t)row * 4096 + (c)*16 + ch * 4);                  \
        }                                                                     \
        CP_COMMIT();                                                          \
    }

    float acc[2][4][4] = {};

    KT_LOAD(0, 0);
    KT_LOAD(1, 1);
    KT_LOAD(2, 2);

#pragma unroll 1
    for (int c = 0; c < 64; c++) {
        if (c < 61) { CP_WAIT(2); } else { CP_WAIT(0); }
        __syncthreads();
        if (c + 3 < 64) KT_LOAD((c + 3) & 3, c + 3);

        const float* A = sA + (c & 3) * 2560;
        const float* B = sB + (c & 3) * 1280;
#pragma unroll
        for (int h = 0; h < 2; h++) {
            const int ks = h * 8;
            uint32_t b0[4], b1[4];
#pragma unroll
            for (int fn = 0; fn < 4; fn++) {
                int n0 = wn + fn * 8 + gid;
                b0[fn] = FRAG_U(B[n0 * 20 + ks + tig]);
                b1[fn] = FRAG_U(B[n0 * 20 + ks + tig + 4]);
            }
#pragma unroll
            for (int fm = 0; fm < 2; fm++) {
                int m0 = wm + fm * 16 + gid;
                uint32_t a0 = FRAG_U(A[m0 * 20 + ks + tig]);
                uint32_t a1 = FRAG_U(A[(m0 + 8) * 20 + ks + tig]);
                uint32_t a2 = FRAG_U(A[m0 * 20 + ks + tig + 4]);
                uint32_t a3 = FRAG_U(A[(m0 + 8) * 20 + ks + tig + 4]);
#pragma unroll
                for (int fn = 0; fn < 4; fn++)
                    mma_tf32(acc[fm][fn], a0, a1, a2, a3, b0[fn], b1[fn]);
            }
        }
        __syncthreads();
    }
#undef KT_LOAD

    float* Tb = g_T + (size_t)(b * 512 + mBase) * 64;
#pragma unroll
    for (int fm = 0; fm < 2; fm++) {
        int m0 = wm + fm * 16 + gid;
#pragma unroll
        for (int fn = 0; fn < 4; fn++) {
            int n0 = wn + fn * 8 + tig * 2;
            atomicAdd(&Tb[m0 * 64 + n0], acc[fm][fn][0]);
            atomicAdd(&Tb[m0 * 64 + n0 + 1], acc[fm][fn][1]);
            atomicAdd(&Tb[(m0 + 8) * 64 + n0], acc[fm][fn][2]);
            atomicAdd(&Tb[(m0 + 8) * 64 + n0 + 1], acc[fm][fn][3]);
        }
    }
}

// ---------------------------------------------------------------------------
// K_energy: g_E[b,k,q] += sum_{c in split} key_w[k,c]*T[b,c,q]  (fp32)
// grid (4 csplit, 16 b), 256 threads, 64x64 tile, 4x4 micro
// ---------------------------------------------------------------------------
__global__ __launch_bounds__(256) void k_energy(const float* __restrict__ key_w) {
    __shared__ float sA[64][68];  // key_w chunk transposed [c][k]
    __shared__ float sB[64][68];  // T chunk [c][q]
    const int tid = threadIdx.x;
    const int tx = tid & 15, ty = tid >> 4;
    const int b = blockIdx.y, cs = blockIdx.x * 128;
    const int r0 = tid >> 4, c4 = tid & 15;

    float acc[4][4] = {};
#pragma unroll
    for (int ch = 0; ch < 2; ch++) {
        int cb = cs + ch * 64;
#pragma unroll
        for (int p = 0; p < 4; p++) {
            int r = r0 + p * 16;
            float4 fk = *(const float4*)&key_w[r * 512 + cb + c4 * 4];
            sA[c4 * 4 + 0][r] = fk.x; sA[c4 * 4 + 1][r] = fk.y;
            sA[c4 * 4 + 2][r] = fk.z; sA[c4 * 4 + 3][r] = fk.w;
            float4 ft =
                *(const float4*)&g_T[(size_t)(b * 512 + cb + r) * 64 + c4 * 4];
            *(float4*)&sB[r][c4 * 4] = ft;
        }
        __syncthreads();
#pragma unroll 16
        for (int cc = 0; cc < 64; cc++) {
            float a[4], bq[4];
            *(float4*)a = *(const float4*)&sA[cc][ty * 4];
            *(float4*)bq = *(const float4*)&sB[cc][tx * 4];
#pragma unroll
            for (int i = 0; i < 4; i++)
#pragma unroll
                for (int j = 0; j < 4; j++) acc[i][j] += a[i] * bq[j];
        }
        __syncthreads();
    }

    float* Eb = g_E + b * 4096;
#pragma unroll
    for (int i = 0; i < 4; i++)
#pragma unroll
        for (int j = 0; j < 4; j++)
            atomicAdd(&Eb[(ty * 4 + i) * 64 + tx * 4 + j], acc[i][j]);
}

// ---------------------------------------------------------------------------
// K_soft: energy += key_b*S ; softmax rows ; W2' = scale1*(c1_w @ attn)
// grid 16, 256 threads
// ---------------------------------------------------------------------------
__global__ __launch_bounds__(256) void k_soft(const float* __restrict__ key_b,
                                              const float* __restrict__ c1_w,
                                              const float* __restrict__ c1_gamma,
                                              const float* __restrict__ c1_var) {
    __shared__ float sE[64][65];
    const int tid = threadIdx.x;
    const int b = blockIdx.x;

    for (int t = tid; t < 4096; t += 256) {
        int k = t >> 6, q = t & 63;
        sE[k][q] = g_E[b * 4096 + t] + key_b[k] * g_S[b * 64 + q];
    }
    __syncthreads();

    if (tid < 64) {
        float mx = -1e30f;
        for (int q = 0; q < 64; q++) mx = fmaxf(mx, sE[tid][q]);
        float sum = 0.f;
        for (int q = 0; q < 64; q++) {
            float e = expf(sE[tid][q] - mx);
            sE[tid][q] = e;
            sum += e;
        }
        float inv = 1.f / sum;
        for (int q = 0; q < 64; q++) sE[tid][q] *= inv;
    }
    __syncthreads();

    for (int t = tid; t < 4096; t += 256) {
        int o = t >> 6, q = t & 63;
        float s = 0.f;
#pragma unroll 16
        for (int k = 0; k < 64; k++) s += c1_w[o * 64 + k] * sE[k][q];
        float sc = c1_gamma[o] * rsqrtf(c1_var[o] + EPSB);
        g_W2[(b * 64 + o) * 64 + q] = sc * s;
    }
}

// ---------------------------------------------------------------------------
// K_mid: mid[b,o,n] = tf32(relu( sum_q W2'[b,o,q]*att[b,q,n] + bias1[o] ))
// ---------------------------------------------------------------------------
__global__ __launch_bounds__(256) void k_mid(const float* __restrict__ att,
                                             const float* __restrict__ c1_b,
                                             const float* __restrict__ c1_gamma,
                                             const float* __restrict__ c1_beta,
                                             const float* __restrict__ c1_mean,
                                             const float* __restrict__ c1_var) {
    __shared__ float w2t[64][68];
    __shared__ float as[64][68];
    __shared__ float bi1[64];
    const int tid = threadIdx.x;
    const int tx = tid & 15, ty = tid >> 4;
    const int b = blockIdx.y, nb = blockIdx.x * 64;
    const int r0 = tid >> 4, c4 = tid & 15;

    if (tid < 64) {
        float sc = c1_gamma[tid] * rsqrtf(c1_var[tid] + EPSB);
        bi1[tid] = sc * c1_b[tid] + c1_beta[tid] - c1_mean[tid] * sc;
    }
#pragma unroll
    for (int p = 0; p < 4; p++) {
        int r = r0 + p * 16;
        float4 fw = *(const float4*)&g_W2[(size_t)(b * 64 + r) * 64 + c4 * 4];
        w2t[c4 * 4 + 0][r] = fw.x; w2t[c4 * 4 + 1][r] = fw.y;
        w2t[c4 * 4 + 2][r] = fw.z; w2t[c4 * 4 + 3][r] = fw.w;
        float4 fa = *(const float4*)&att[(size_t)(b * 64 + r) * 4096 + nb + c4 * 4];
        *(float4*)&as[r][c4 * 4] = fa;
    }
    __syncthreads();

    float acc[4][4] = {};
#pragma unroll 16
    for (int q = 0; q < 64; q++) {
        float a[4], bq[4];
        *(float4*)a = *(const float4*)&w2t[q][ty * 4];
        *(float4*)bq = *(const float4*)&as[q][tx * 4];
#pragma unroll
        for (int i = 0; i < 4; i++)
#pragma unroll
            for (int j = 0; j < 4; j++) acc[i][j] += a[i] * bq[j];
    }

    float* mb = g_mid + (size_t)(b * 64) * 4096 + nb;
#pragma unroll
    for (int i = 0; i < 4; i++) {
        int o = ty * 4 + i;
        float bi = bi1[o];
        float4 v;
        v.x = fmaxf(acc[i][0] + bi, 0.f);
        v.y = fmaxf(acc[i][1] + bi, 0.f);
        v.z = fmaxf(acc[i][2] + bi, 0.f);
        v.w = fmaxf(acc[i][3] + bi, 0.f);
        *(float4*)&mb[(size_t)o * 4096 + tx * 4] = cvt4(v);
    }
}

// ---------------------------------------------------------------------------
// K_out (mma tf32 + cp.async 4-stage): out = relu(scale2*(c2_w@[mid;x])+bias2')
// Block 128x128, 8 warps 2m x 4n (warp 64x32), K=576 in 36 chunks of 16.
// A smem [m128][k16 pitch20]; B smem [k16][n128 pitch136].
// grid (32 n, 4 m, 16 b), 256 threads, 2 CTA/SM.
// ---------------------------------------------------------------------------
__global__ __launch_bounds__(256, 2) void k_out_mma(
    const float* __restrict__ c2_b, const float* __restrict__ c2_gamma,
    const float* __restrict__ c2_beta, const float* __restrict__ c2_mean,
    const float* __restrict__ c2_var, float* __restrict__ out) {
    extern __shared__ float dsm[];
    float* sA = dsm;           // 4 stages x 2560 floats
    float* sB = dsm + 10240;   // 4 stages x 2176 floats
    const uint32_t sAu = smem_u32(sA), sBu = smem_u32(sB);
    __shared__ float sc2s[128], bi2s[128];

    const int tid = threadIdx.x;
    const int wid = tid >> 5, lane = tid & 31;
    const int gid = lane >> 2, tig = lane & 3;
    const int wm = (wid >> 2) * 64, wn = (wid & 3) * 32;
    const int nBase = blockIdx.x * 128, mBase = blockIdx.y * 128;
    const int b = blockIdx.z;

    const float* wA = g_w2c + (size_t)mBase * 576;
    const float* midb = g_mid + (size_t)b * 64 * 4096;
    const float* xb = g_x32 + (size_t)b * 512 * 4096;

    if (tid < 128) {
        int m = mBase + tid;
        float sc = c2_gamma[m] * rsqrtf(c2_var[m] + EPSB);
        sc2s[tid] = sc;
        bi2s[tid] = sc * c2_b[m] + c2_beta[m] - c2_mean[m] * sc;
    }

#define KO_LOAD(st, c)                                                        \
    {                                                                         \
        _Pragma("unroll") for (int j = 0; j < 2; j++) {                       \
            int idx = tid * 2 + j;                                            \
            int row = idx >> 2, ch = idx & 3;                                 \
            cp16(sAu + (st)*10240 + row * 80 + ch * 16,                       \
                 wA + (size_t)row * 576 + (c)*16 + ch * 4);                   \
        }                                                                     \
        _Pragma("unroll") for (int j = 0; j < 2; j++) {                       \
            int idx = tid * 2 + j;                                            \
            int row = idx >> 5, ch = idx & 31;                                \
            int kg = (c)*16 + row;                                            \
            const float* src = (kg < 64) ? (midb + (size_t)kg * 4096)         \
                                         : (xb + (size_t)(kg - 64) * 4096);  \
            cp16(sBu + (st)*8704 + row * 544 + ch * 16,                       \
                 src + nBase + ch * 4);                                       \
        }                                                                     \
        CP_COMMIT();                                                          \
    }

    float acc[4][4][4] = {};

    KO_LOAD(0, 0);
    KO_LOAD(1, 1);
    KO_LOAD(2, 2);

#pragma unroll 1
    for (int c = 0; c < 36; c++) {
        if (c < 33) { CP_WAIT(2); } else { CP_WAIT(0); }
        __syncthreads();
        if (c + 3 < 36) KO_LOAD((c + 3) & 3, c + 3);

        const float* A = sA + (c & 3) * 2560;
        const float* B = sB + (c & 3) * 2176;
#pragma unroll
        for (int h = 0; h < 2; h++) {
            const int ks = h * 8;
            uint32_t b0[4], b1[4];
#pragma unroll
            for (int fn = 0; fn < 4; fn++) {
                int n0 = wn + fn * 8 + gid;
                b0[fn] = FRAG_U(B[(ks + tig) * 136 + n0]);
                b1[fn] = FRAG_U(B[(ks + tig + 4) * 136 + n0]);
            }
#pragma unroll
            for (int fm = 0; fm < 4; fm++) {
                int m0 = wm + fm * 16 + gid;
                uint32_t a0 = FRAG_U(A[m0 * 20 + ks + tig]);
                uint32_t a1 = FRAG_U(A[(m0 + 8) * 20 + ks + tig]);
                uint32_t a2 = FRAG_U(A[m0 * 20 + ks + tig + 4]);
                uint32_t a3 = FRAG_U(A[(m0 + 8) * 20 + ks + tig + 4]);
#pragma unroll
                for (int fn = 0; fn < 4; fn++)
                    mma_tf32(acc[fm][fn], a0, a1, a2, a3, b0[fn], b1[fn]);
            }
        }
        __syncthreads();
    }
#undef KO_LOAD

    float* outb = out + (size_t)b * 512 * 4096;
#pragma unroll
    for (int fm = 0; fm < 4; fm++) {
        const int ml0 = wm + fm * 16 + gid;
        const float s0 = sc2s[ml0], v0 = bi2s[ml0];
        const float s1 = sc2s[ml0 + 8], v1 = bi2s[ml0 + 8];
        float* r0 = outb + (size_t)(mBase + ml0) * 4096 + nBase + wn;
        float* r1 = r0 + (size_t)8 * 4096;
#pragma unroll
        for (int fn = 0; fn < 4; fn++) {
            const int nc = fn * 8 + 2 * tig;
            float2 w0, w1;
            w0.x = fmaxf(acc[fm][fn][0] * s0 + v0, 0.f);
            w0.y = fmaxf(acc[fm][fn][1] * s0 + v0, 0.f);
            w1.x = fmaxf(acc[fm][fn][2] * s1 + v1, 0.f);
            w1.y = fmaxf(acc[fm][fn][3] * s1 + v1, 0.f);
            *(float2*)&r0[nc] = w0;
            *(float2*)&r1[nc] = w1;
        }
    }
}

// ---------------------------------------------------------------------------
extern "C" void kernel_launch(void* const* d_in, const int* in_sizes, int n_in,
                              void* d_out, int out_size) {
    const float* x        = (const float*)d_in[0];
    const float* att      = (const float*)d_in[1];
    const float* key_w    = (const float*)d_in[2];
    const float* key_b    = (const float*)d_in[3];
    const float* c1_w     = (const float*)d_in[4];
    const float* c1_b     = (const float*)d_in[5];
    const float* c1_gamma = (const float*)d_in[6];
    const float* c1_beta  = (const float*)d_in[7];
    const float* c1_mean  = (const float*)d_in[8];
    const float* c1_var   = (const float*)d_in[9];
    const float* c2_w     = (const float*)d_in[10];
    const float* c2_b     = (const float*)d_in[11];
    const float* c2_gamma = (const float*)d_in[12];
    const float* c2_beta  = (const float*)d_in[13];
    const float* c2_mean  = (const float*)d_in[14];
    const float* c2_var   = (const float*)d_in[15];
    float* out = (float*)d_out;

    cudaFuncSetAttribute(k_T_mma, cudaFuncAttributeMaxDynamicSharedMemorySize,
                         61440);
    cudaFuncSetAttribute(k_out_mma,
                         cudaFuncAttributeMaxDynamicSharedMemorySize, 75776);

    k_prep<<<2048, 256>>>(x, att, c2_w);
    k_sumS<<<1024, 128>>>(att);
    k_T_mma<<<dim3(4, 4, 16), 256, 61440>>>();
    k_energy<<<dim3(4, 16), 256>>>(key_w);
    k_soft<<<16, 256>>>(key_b, c1_w, c1_gamma, c1_var);
    k_mid<<<dim3(64, 16), 256>>>(att, c1_b, c1_gamma, c1_beta, c1_mean, c1_var);
    k_out_mma<<<dim3(32, 4, 16), 256, 75776>>>(c2_b, c2_gamma, c2_beta,
                                               c2_mean, c2_var, out);
}